// round 3
// baseline (speedup 1.0000x reference)
#include <cuda_runtime.h>

#define Bsz 64
#define Tt  512
#define Ii  512
#define Hh  512

// hidden state, double buffered, k-major: [dir][parity][k*64 + b]
__device__ float g_h[2][2][Hh * Bsz];
// fine-grained ready counters: [dir][step][chunk], chunk = 64 k-rows
__device__ int g_rdy[2][Tt][8];

// ---------------------------------------------------------------------------
// init: zero counters, stage h0 (transposed to k-major)
// ---------------------------------------------------------------------------
__global__ void init_kernel(const float* __restrict__ h0f,
                            const float* __restrict__ h0b) {
    int idx = blockIdx.x * blockDim.x + threadIdx.x;   // 0..32767
    int b = idx >> 9;
    int k = idx & 511;
    g_h[0][0][k * Bsz + b] = h0f[idx];
    g_h[1][0][k * Bsz + b] = h0b[idx];
    if (idx < 2 * Tt * 8) ((int*)g_rdy)[idx] = 0;
}

// ---------------------------------------------------------------------------
// Phase 1: y[b*T+t][j] = x[b,t,:] . W[j,:] + bias[j]   (j in [0,2H))
// ---------------------------------------------------------------------------
#define BM 128
#define BN 64
#define BK 32
#define ASP 132
#define BSP 68

__global__ __launch_bounds__(256) void xproj_kernel(
    const float* __restrict__ x,
    const float* __restrict__ Wxf, const float* __restrict__ bxf,
    const float* __restrict__ Wxb, const float* __restrict__ bxb,
    float* __restrict__ y)
{
    __shared__ float As[BK][ASP];
    __shared__ float Bs[BK][BSP];
    int tid = threadIdx.x;
    int m0 = blockIdx.y * BM;
    int n0 = blockIdx.x * BN;

    const float* W;
    const float* bias;
    int jl;
    if (n0 < Hh) { W = Wxf; bias = bxf; jl = n0; }
    else         { W = Wxb; bias = bxb; jl = n0 - Hh; }

    int tx = tid & 15;   // n: 4 cols each
    int ty = tid >> 4;   // m: 8 rows each

    float acc[8][4];
#pragma unroll
    for (int i = 0; i < 8; i++)
#pragma unroll
        for (int j = 0; j < 4; j++) acc[i][j] = 0.f;

    for (int kc = 0; kc < Ii; kc += BK) {
#pragma unroll
        for (int r = 0; r < 4; ++r) {
            int idx = tid + 256 * r;
            int row = idx >> 3, c4 = idx & 7;
            float4 v = *(const float4*)&x[(m0 + row) * Ii + kc + c4 * 4];
            As[c4 * 4 + 0][row] = v.x;
            As[c4 * 4 + 1][row] = v.y;
            As[c4 * 4 + 2][row] = v.z;
            As[c4 * 4 + 3][row] = v.w;
        }
#pragma unroll
        for (int r = 0; r < 2; ++r) {
            int idx = tid + 256 * r;
            int row = idx >> 3, c4 = idx & 7;
            float4 v = *(const float4*)&W[(jl + row) * Ii + kc + c4 * 4];
            Bs[c4 * 4 + 0][row] = v.x;
            Bs[c4 * 4 + 1][row] = v.y;
            Bs[c4 * 4 + 2][row] = v.z;
            Bs[c4 * 4 + 3][row] = v.w;
        }
        __syncthreads();
#pragma unroll
        for (int kk = 0; kk < BK; ++kk) {
            float4 b4 = *(const float4*)&Bs[kk][tx * 4];
            float4 a0 = *(const float4*)&As[kk][ty * 8];
            float4 a1 = *(const float4*)&As[kk][ty * 8 + 4];
            float av[8] = {a0.x, a0.y, a0.z, a0.w, a1.x, a1.y, a1.z, a1.w};
            float bv[4] = {b4.x, b4.y, b4.z, b4.w};
#pragma unroll
            for (int i = 0; i < 8; i++)
#pragma unroll
                for (int j = 0; j < 4; j++)
                    acc[i][j] = fmaf(av[i], bv[j], acc[i][j]);
        }
        __syncthreads();
    }

    float4 bias4 = *(const float4*)&bias[jl + tx * 4];
#pragma unroll
    for (int i = 0; i < 8; i++) {
        int m = m0 + ty * 8 + i;
        float4 o;
        o.x = acc[i][0] + bias4.x;
        o.y = acc[i][1] + bias4.y;
        o.z = acc[i][2] + bias4.z;
        o.w = acc[i][3] + bias4.w;
        *(float4*)&y[(size_t)m * (2 * Hh) + n0 + tx * 4] = o;
    }
}

// ---------------------------------------------------------------------------
// acquire spin on a chunk-ready counter (all threads spin independently)
// ---------------------------------------------------------------------------
__device__ __forceinline__ void wait_chunk(const int* p) {
    int v;
    do {
        asm volatile("ld.acquire.gpu.global.b32 %0, [%1];"
                     : "=r"(v) : "l"(p) : "memory");
    } while (v < 8);
}

// ---------------------------------------------------------------------------
// Phase 2: persistent recurrence kernel, fine-grained chunk dataflow.
// 128 CTAs: blocks 0..63 forward, 64..127 backward. Each owns 8 hidden cols.
// ---------------------------------------------------------------------------
__global__ __launch_bounds__(256) void rnn_kernel(
    const float* __restrict__ Whf, const float* __restrict__ Whb,
    float* __restrict__ y, float* __restrict__ out_hT)
{
    extern __shared__ float smem[];
    float* sh_wt = smem;                       // [512][8]   transposed Wh slice
    float* sh_ht = smem + 4096;                // 2 x [64][68] h chunk (k-major)
    float* red   = smem + 4096 + 2 * 64 * 68;  // [512][9]   partials
    float* sxp   = red + 512 * 9;              // [512]      xp in / h out

    int tid  = threadIdx.x;
    int bx   = blockIdx.x;
    int dir  = bx >> 6;
    int jblk = (bx & 63) * 8;
    int mychunk = (bx & 63) >> 3;
    const float* Wh = dir ? Whb : Whf;

    // stage Wh slice, transposed to [k][j]
    for (int r = 0; r < 16; ++r) {
        int idx = tid + 256 * r;
        int j = idx >> 9, k = idx & 511;
        sh_wt[k * 8 + j] = Wh[(jblk + j) * Hh + k];
    }
    __syncthreads();

    int sl = tid >> 5;        // warp = k-slice (8 k per 64-chunk)
    int sp = tid & 31;
    int b0 = (sp & 15) * 4;
    int j0 = (sp >> 4) * 4;
    int yhalf = dir * Hh;

    // coalesced y mapping: j fastest (8), then b
    int jy = tid & 7;
    int by = tid >> 3;        // 0..31 ; second element by+32

    for (int s = 0; s < Tt; ++s) {
        int t = dir ? (Tt - 1 - s) : s;
        const float* hsrc = g_h[dir][s & 1];
        float* hdst       = g_h[dir][(s + 1) & 1];

        size_t ycol = (size_t)t * (2 * Hh) + yhalf + jblk + jy;
        // load xp coalesced, stage to smem
        float xpa = y[(size_t)by * (Tt * 2 * Hh) + ycol];
        float xpb = y[(size_t)(by + 32) * (Tt * 2 * Hh) + ycol];
        sxp[jy * 64 + by]      = xpa;
        sxp[jy * 64 + by + 32] = xpb;

        float acc[4][4];
#pragma unroll
        for (int i = 0; i < 4; i++)
#pragma unroll
            for (int j = 0; j < 4; j++) acc[i][j] = 0.f;

        // chunk loop with per-chunk ready-wait + double-buffered prefetch
        int pc = mychunk;                       // chunk being prefetched
        if (s > 0) wait_chunk(&g_rdy[dir][s - 1][pc]);
        float4 pf[4];
#pragma unroll
        for (int r = 0; r < 4; ++r) {
            int idx = tid + 256 * r;
            int kk = idx >> 4, b4 = idx & 15;
            pf[r] = __ldcg((const float4*)&hsrc[(pc * 64 + kk) * Bsz + b4 * 4]);
        }
        int cur = 0;
        int staged = pc;                        // chunk staged into smem
        for (int c = 0; c < 8; ++c) {
            float* buf = sh_ht + cur * (64 * 68);
#pragma unroll
            for (int r = 0; r < 4; ++r) {
                int idx = tid + 256 * r;
                int kk = idx >> 4, b4 = idx & 15;
                *(float4*)&buf[kk * 68 + b4 * 4] = pf[r];
            }
            __syncthreads();
            int kbase = staged * 64;
            if (c < 7) {
                pc = (mychunk + c + 1) & 7;
                if (s > 0) wait_chunk(&g_rdy[dir][s - 1][pc]);
#pragma unroll
                for (int r = 0; r < 4; ++r) {
                    int idx = tid + 256 * r;
                    int kk = idx >> 4, b4 = idx & 15;
                    pf[r] = __ldcg(
                        (const float4*)&hsrc[(pc * 64 + kk) * Bsz + b4 * 4]);
                }
            }
#pragma unroll
            for (int u = 0; u < 8; ++u) {
                int kk = sl * 8 + u;
                float4 h4 = *(const float4*)&buf[kk * 68 + b0];
                float4 w4 = *(const float4*)&sh_wt[(kbase + kk) * 8 + j0];
                float hv[4] = {h4.x, h4.y, h4.z, h4.w};
                float wv[4] = {w4.x, w4.y, w4.z, w4.w};
#pragma unroll
                for (int ji = 0; ji < 4; ji++)
#pragma unroll
                    for (int bi = 0; bi < 4; bi++)
                        acc[ji][bi] = fmaf(wv[ji], hv[bi], acc[ji][bi]);
            }
            staged = pc;
            cur ^= 1;
        }
        __syncthreads();
        // write partials
#pragma unroll
        for (int ji = 0; ji < 4; ji++)
#pragma unroll
            for (int bi = 0; bi < 4; bi++)
                red[((j0 + ji) * 64 + (b0 + bi)) * 9 + sl] = acc[ji][bi];
        __syncthreads();

        // gather + tanh (o-mapping: conflict-free red, coalesced hdst)
        {
            int o1 = tid, o2 = tid + 256;
            float v1 = sxp[o1], v2 = sxp[o2];
#pragma unroll
            for (int q = 0; q < 8; ++q) {
                v1 += red[o1 * 9 + q];
                v2 += red[o2 * 9 + q];
            }
            v1 = tanhf(v1);
            v2 = tanhf(v2);
            hdst[(jblk + (o1 >> 6)) * Bsz + (o1 & 63)] = v1;
            hdst[(jblk + (o2 >> 6)) * Bsz + (o2 & 63)] = v2;
            sxp[o1] = v1;
            sxp[o2] = v2;
            if (s == Tt - 1) {
                float* ht = out_hT + (size_t)dir * (Bsz * Hh);
                ht[(o1 & 63) * Hh + jblk + (o1 >> 6)] = v1;
                ht[(o2 & 63) * Hh + jblk + (o2 >> 6)] = v2;
            }
        }
        __threadfence();
        __syncthreads();
        if (tid == 0) atomicAdd(&g_rdy[dir][s][mychunk], 1);

        // coalesced y write from smem
        y[(size_t)by * (Tt * 2 * Hh) + ycol]        = sxp[jy * 64 + by];
        y[(size_t)(by + 32) * (Tt * 2 * Hh) + ycol] = sxp[jy * 64 + by + 32];
        __syncthreads();   // protect sxp before next step overwrites
    }
}

// ---------------------------------------------------------------------------
extern "C" void kernel_launch(void* const* d_in, const int* in_sizes, int n_in,
                              void* d_out, int out_size) {
    const float* x    = (const float*)d_in[0];
    const float* h0_f = (const float*)d_in[1];
    const float* h0_b = (const float*)d_in[2];
    const float* Wxf_w = (const float*)d_in[3];
    const float* Wxf_b = (const float*)d_in[4];
    const float* Whf_w = (const float*)d_in[5];
    const float* Wxb_w = (const float*)d_in[6];
    const float* Wxb_b = (const float*)d_in[7];
    const float* Whb_w = (const float*)d_in[8];

    float* y  = (float*)d_out;
    float* hT = y + (size_t)Bsz * Tt * 2 * Hh;

    cudaFuncSetAttribute(rnn_kernel,
                         cudaFuncAttributeMaxDynamicSharedMemorySize,
                         76 * 1024);

    init_kernel<<<64, 512>>>(h0_f, h0_b);

    dim3 grid(2 * Hh / BN, (Bsz * Tt) / BM);
    xproj_kernel<<<grid, 256>>>(x, Wxf_w, Wxf_b, Wxb_w, Wxb_b, y);

    rnn_kernel<<<128, 256, 76 * 1024>>>(Whf_w, Whb_w, y, hT);
    (void)in_sizes; (void)n_in; (void)out_size;
}

// round 4
// speedup vs baseline: 1.2958x; 1.2958x over previous
#include <cuda_runtime.h>

#define Bsz 64
#define Tt  512
#define Ii  512
#define Hh  512

// hidden state, double buffered, k-major: [dir][parity][k*64 + b]
__device__ float g_h[2][2][Hh * Bsz];
// per-step arrival counters per direction
__device__ int g_cnt[2][Tt];

// ---------------------------------------------------------------------------
// init: zero counters, stage h0 (transposed to k-major)
// ---------------------------------------------------------------------------
__global__ void init_kernel(const float* __restrict__ h0f,
                            const float* __restrict__ h0b) {
    int idx = blockIdx.x * blockDim.x + threadIdx.x;   // 0..32767
    int b = idx >> 9;
    int k = idx & 511;
    g_h[0][0][k * Bsz + b] = h0f[idx];
    g_h[1][0][k * Bsz + b] = h0b[idx];
    if (idx < 2 * Tt) ((int*)g_cnt)[idx] = 0;
}

// ---------------------------------------------------------------------------
// Phase 1: y[b*T+t][j] = x[b,t,:] . W[j,:] + bias[j]   (j in [0,2H))
// ---------------------------------------------------------------------------
#define BM 128
#define BN 64
#define BK 32
#define ASP 132
#define BSP 68

__global__ __launch_bounds__(256) void xproj_kernel(
    const float* __restrict__ x,
    const float* __restrict__ Wxf, const float* __restrict__ bxf,
    const float* __restrict__ Wxb, const float* __restrict__ bxb,
    float* __restrict__ y)
{
    __shared__ float As[BK][ASP];
    __shared__ float Bs[BK][BSP];
    int tid = threadIdx.x;
    int m0 = blockIdx.y * BM;
    int n0 = blockIdx.x * BN;

    const float* W;
    const float* bias;
    int jl;
    if (n0 < Hh) { W = Wxf; bias = bxf; jl = n0; }
    else         { W = Wxb; bias = bxb; jl = n0 - Hh; }

    int tx = tid & 15;   // n: 4 cols each
    int ty = tid >> 4;   // m: 8 rows each

    float acc[8][4];
#pragma unroll
    for (int i = 0; i < 8; i++)
#pragma unroll
        for (int j = 0; j < 4; j++) acc[i][j] = 0.f;

    for (int kc = 0; kc < Ii; kc += BK) {
#pragma unroll
        for (int r = 0; r < 4; ++r) {
            int idx = tid + 256 * r;
            int row = idx >> 3, c4 = idx & 7;
            float4 v = *(const float4*)&x[(m0 + row) * Ii + kc + c4 * 4];
            As[c4 * 4 + 0][row] = v.x;
            As[c4 * 4 + 1][row] = v.y;
            As[c4 * 4 + 2][row] = v.z;
            As[c4 * 4 + 3][row] = v.w;
        }
#pragma unroll
        for (int r = 0; r < 2; ++r) {
            int idx = tid + 256 * r;
            int row = idx >> 3, c4 = idx & 7;
            float4 v = *(const float4*)&W[(jl + row) * Ii + kc + c4 * 4];
            Bs[c4 * 4 + 0][row] = v.x;
            Bs[c4 * 4 + 1][row] = v.y;
            Bs[c4 * 4 + 2][row] = v.z;
            Bs[c4 * 4 + 3][row] = v.w;
        }
        __syncthreads();
#pragma unroll
        for (int kk = 0; kk < BK; ++kk) {
            float4 b4 = *(const float4*)&Bs[kk][tx * 4];
            float4 a0 = *(const float4*)&As[kk][ty * 8];
            float4 a1 = *(const float4*)&As[kk][ty * 8 + 4];
            float av[8] = {a0.x, a0.y, a0.z, a0.w, a1.x, a1.y, a1.z, a1.w};
            float bv[4] = {b4.x, b4.y, b4.z, b4.w};
#pragma unroll
            for (int i = 0; i < 8; i++)
#pragma unroll
                for (int j = 0; j < 4; j++)
                    acc[i][j] = fmaf(av[i], bv[j], acc[i][j]);
        }
        __syncthreads();
    }

    float4 bias4 = *(const float4*)&bias[jl + tx * 4];
#pragma unroll
    for (int i = 0; i < 8; i++) {
        int m = m0 + ty * 8 + i;
        float4 o;
        o.x = acc[i][0] + bias4.x;
        o.y = acc[i][1] + bias4.y;
        o.z = acc[i][2] + bias4.z;
        o.w = acc[i][3] + bias4.w;
        *(float4*)&y[(size_t)m * (2 * Hh) + n0 + tx * 4] = o;
    }
}

// ---------------------------------------------------------------------------
// Phase 2: persistent recurrence kernel.
// 128 CTAs: blocks 0..63 forward, 64..127 backward. Each owns 8 hidden cols.
// Per-warp private k-slice (64 rows) with per-warp double-buffered staging:
// no CTA-wide syncs inside the k loop, only __syncwarp.
// ---------------------------------------------------------------------------
__global__ __launch_bounds__(256) void rnn_kernel(
    const float* __restrict__ Whf, const float* __restrict__ Whb,
    float* __restrict__ y, float* __restrict__ out_hT)
{
    extern __shared__ float smem[];
    float* sh_wt = smem;                        // [512][8] transposed Wh slice
    float* sh_h  = smem + 4096;                 // 8 warps x 2 x [8][68]
    float* red   = sh_h + 8 * 2 * 8 * 68;       // [8][520] partials
    float* sxp   = red + 8 * 520;               // [512] xp in / h out

    int tid  = threadIdx.x;
    int bx   = blockIdx.x;
    int dir  = bx >> 6;
    int jblk = (bx & 63) * 8;
    const float* Wh = dir ? Whb : Whf;

    // stage Wh slice, transposed to [k][j]
    for (int r = 0; r < 16; ++r) {
        int idx = tid + 256 * r;
        int j = idx >> 9, k = idx & 511;
        sh_wt[k * 8 + j] = Wh[(jblk + j) * Hh + k];
    }
    __syncthreads();

    int sl = tid >> 5;            // warp id = k-slice (64 k rows each)
    int sp = tid & 31;
    int b0 = (sp & 15) * 4;
    int j0 = (sp >> 4) * 4;
    int warpk0 = sl * 64;
    float* wbuf = sh_h + sl * (2 * 8 * 68);
    int yhalf = dir * Hh;

    // coalesced y mapping: j fastest
    int jy = tid & 7;
    int by = tid >> 3;            // 0..31 ; second element by+32

    int o1 = tid, o2 = tid + 256;
    int jo1 = o1 >> 6, bo1 = o1 & 63;
    int jo2 = o2 >> 6, bo2 = o2 & 63;

    for (int s = 0; s < Tt; ++s) {
        int t = dir ? (Tt - 1 - s) : s;
        const float* hsrc = g_h[dir][s & 1];
        float* hdst       = g_h[dir][(s + 1) & 1];

        size_t ycol = (size_t)t * (2 * Hh) + yhalf + jblk + jy;
        float xpa = y[(size_t)by * (Tt * 2 * Hh) + ycol];
        float xpb = y[(size_t)(by + 32) * (Tt * 2 * Hh) + ycol];

        float acc[4][4];
#pragma unroll
        for (int i = 0; i < 4; i++)
#pragma unroll
            for (int j = 0; j < 4; j++) acc[i][j] = 0.f;

        // per-warp k-slice: 64k x 64b = 16KB contiguous, 8 sub-chunks of 8k
        const float* gsrc = hsrc + warpk0 * Bsz;
        float4 pf[4];
#pragma unroll
        for (int r = 0; r < 4; ++r)
            pf[r] = __ldcg((const float4*)&gsrc[(sp + 32 * r) * 4]);
        int cur = 0;
        for (int c = 0; c < 8; ++c) {
            float* buf = wbuf + cur * (8 * 68);
#pragma unroll
            for (int r = 0; r < 4; ++r) {
                int idx = sp + 32 * r;
                int kk = idx >> 4, b4 = idx & 15;
                *(float4*)&buf[kk * 68 + b4 * 4] = pf[r];
            }
            if (c < 7) {
#pragma unroll
                for (int r = 0; r < 4; ++r)
                    pf[r] = __ldcg((const float4*)
                                   &gsrc[(c + 1) * 512 + (sp + 32 * r) * 4]);
            }
            __syncwarp();
            int kb = warpk0 + c * 8;
#pragma unroll
            for (int u = 0; u < 8; ++u) {
                float4 h4 = *(const float4*)&buf[u * 68 + b0];
                float4 w4 = *(const float4*)&sh_wt[(kb + u) * 8 + j0];
                float hv[4] = {h4.x, h4.y, h4.z, h4.w};
                float wv[4] = {w4.x, w4.y, w4.z, w4.w};
#pragma unroll
                for (int ji = 0; ji < 4; ji++)
#pragma unroll
                    for (int bi = 0; bi < 4; bi++)
                        acc[ji][bi] = fmaf(wv[ji], hv[bi], acc[ji][bi]);
            }
            cur ^= 1;
        }

        // stage xp + partials, one barrier
        sxp[jy * 64 + by]      = xpa;
        sxp[jy * 64 + by + 32] = xpb;
#pragma unroll
        for (int ji = 0; ji < 4; ji++) {
            float4 v;
            v.x = acc[ji][0]; v.y = acc[ji][1];
            v.z = acc[ji][2]; v.w = acc[ji][3];
            *(float4*)&red[sl * 520 + (j0 + ji) * 64 + b0] = v;
        }
        __syncthreads();

        // gather + tanh
        float v1 = sxp[o1], v2 = sxp[o2];
#pragma unroll
        for (int q = 0; q < 8; ++q) {
            v1 += red[q * 520 + o1];
            v2 += red[q * 520 + o2];
        }
        v1 = tanhf(v1);
        v2 = tanhf(v2);
        hdst[(jblk + jo1) * Bsz + bo1] = v1;
        hdst[(jblk + jo2) * Bsz + bo2] = v2;
        sxp[o1] = v1;
        sxp[o2] = v2;
        if (s == Tt - 1) {
            float* ht = out_hT + (size_t)dir * (Bsz * Hh);
            ht[bo1 * Hh + jblk + jo1] = v1;
            ht[bo2 * Hh + jblk + jo2] = v2;
        }

        __threadfence();
        __syncthreads();
        if (tid == 0) atomicAdd(&g_cnt[dir][s], 1);

        // coalesced y write (overlaps the spin below)
        y[(size_t)by * (Tt * 2 * Hh) + ycol]        = sxp[jy * 64 + by];
        y[(size_t)(by + 32) * (Tt * 2 * Hh) + ycol] = sxp[jy * 64 + by + 32];

        if (s < Tt - 1) {
            if (tid == 0) {
                int v;
                do {
                    asm volatile("ld.acquire.gpu.global.b32 %0, [%1];"
                                 : "=r"(v) : "l"(&g_cnt[dir][s]) : "memory");
                } while (v < 64);
            }
            __syncthreads();
        } else {
            __syncthreads();   // protect sxp (none after, but keep uniform)
        }
    }
}

// ---------------------------------------------------------------------------
extern "C" void kernel_launch(void* const* d_in, const int* in_sizes, int n_in,
                              void* d_out, int out_size) {
    const float* x    = (const float*)d_in[0];
    const float* h0_f = (const float*)d_in[1];
    const float* h0_b = (const float*)d_in[2];
    const float* Wxf_w = (const float*)d_in[3];
    const float* Wxf_b = (const float*)d_in[4];
    const float* Whf_w = (const float*)d_in[5];
    const float* Wxb_w = (const float*)d_in[6];
    const float* Wxb_b = (const float*)d_in[7];
    const float* Whb_w = (const float*)d_in[8];

    float* y  = (float*)d_out;
    float* hT = y + (size_t)Bsz * Tt * 2 * Hh;

    cudaFuncSetAttribute(rnn_kernel,
                         cudaFuncAttributeMaxDynamicSharedMemorySize,
                         72 * 1024);

    init_kernel<<<64, 512>>>(h0_f, h0_b);

    dim3 grid(2 * Hh / BN, (Bsz * Tt) / BM);
    xproj_kernel<<<grid, 256>>>(x, Wxf_w, Wxf_b, Wxb_w, Wxb_b, y);

    rnn_kernel<<<128, 256, 72 * 1024>>>(Whf_w, Whb_w, y, hT);
    (void)in_sizes; (void)n_in; (void)out_size;
}

// round 14
// speedup vs baseline: 1.4852x; 1.1462x over previous
#include <cuda_runtime.h>
#include <cuda_bf16.h>
#include <cstdint>

#define Bsz 64
#define Tt  512
#define Ii  512
#define Hh  512

// hidden state, double buffered, k-major: [dir][parity][k*64 + b]
__device__ float g_h[2][2][Hh * Bsz];
// per-step arrival counters per direction
__device__ int g_cnt[2][Tt];

// bf16 split operands for the xproj GEMM
__device__ __nv_bfloat16 g_xh[32768 * 512];
__device__ __nv_bfloat16 g_xl[32768 * 512];
__device__ __nv_bfloat16 g_wh[1024 * 512];
__device__ __nv_bfloat16 g_wl[1024 * 512];
__device__ float g_bias[1024];

// ---------------------------------------------------------------------------
// init: zero counters, stage h0 (transposed to k-major)
// ---------------------------------------------------------------------------
__global__ void init_kernel(const float* __restrict__ h0f,
                            const float* __restrict__ h0b) {
    int idx = blockIdx.x * blockDim.x + threadIdx.x;   // 0..32767
    int b = idx >> 9;
    int k = idx & 511;
    g_h[0][0][k * Bsz + b] = h0f[idx];
    g_h[1][0][k * Bsz + b] = h0b[idx];
    if (idx < 2 * Tt) ((int*)g_cnt)[idx] = 0;
}

// ---------------------------------------------------------------------------
// split fp32 -> bf16 hi/lo
// ---------------------------------------------------------------------------
__global__ __launch_bounds__(256) void split_x_kernel(const float* __restrict__ x) {
    int idx = blockIdx.x * blockDim.x + threadIdx.x;   // 0..4194303
    float4 v = ((const float4*)x)[idx];
    __nv_bfloat16 h0 = __float2bfloat16(v.x);
    __nv_bfloat16 h1 = __float2bfloat16(v.y);
    __nv_bfloat16 h2 = __float2bfloat16(v.z);
    __nv_bfloat16 h3 = __float2bfloat16(v.w);
    __nv_bfloat16 l0 = __float2bfloat16(v.x - __bfloat162float(h0));
    __nv_bfloat16 l1 = __float2bfloat16(v.y - __bfloat162float(h1));
    __nv_bfloat16 l2 = __float2bfloat16(v.z - __bfloat162float(h2));
    __nv_bfloat16 l3 = __float2bfloat16(v.w - __bfloat162float(h3));
    __nv_bfloat162 ph0; ph0.x = h0; ph0.y = h1;
    __nv_bfloat162 ph1; ph1.x = h2; ph1.y = h3;
    __nv_bfloat162 pl0; pl0.x = l0; pl0.y = l1;
    __nv_bfloat162 pl1; pl1.x = l2; pl1.y = l3;
    ((__nv_bfloat162*)g_xh)[idx * 2]     = ph0;
    ((__nv_bfloat162*)g_xh)[idx * 2 + 1] = ph1;
    ((__nv_bfloat162*)g_xl)[idx * 2]     = pl0;
    ((__nv_bfloat162*)g_xl)[idx * 2 + 1] = pl1;
}

__global__ __launch_bounds__(256) void split_w_kernel(
    const float* __restrict__ Wxf, const float* __restrict__ Wxb,
    const float* __restrict__ bxf, const float* __restrict__ bxb) {
    int idx = blockIdx.x * blockDim.x + threadIdx.x;   // 0..131071
    int j = idx >> 7;               // 0..1023
    int c4 = (idx & 127) * 4;
    const float* src = (j < 512) ? &Wxf[j * 512 + c4]
                                 : &Wxb[(j - 512) * 512 + c4];
    float4 v = *(const float4*)src;
    __nv_bfloat16 h0 = __float2bfloat16(v.x);
    __nv_bfloat16 h1 = __float2bfloat16(v.y);
    __nv_bfloat16 h2 = __float2bfloat16(v.z);
    __nv_bfloat16 h3 = __float2bfloat16(v.w);
    __nv_bfloat16 l0 = __float2bfloat16(v.x - __bfloat162float(h0));
    __nv_bfloat16 l1 = __float2bfloat16(v.y - __bfloat162float(h1));
    __nv_bfloat16 l2 = __float2bfloat16(v.z - __bfloat162float(h2));
    __nv_bfloat16 l3 = __float2bfloat16(v.w - __bfloat162float(h3));
    __nv_bfloat162 ph0; ph0.x = h0; ph0.y = h1;
    __nv_bfloat162 ph1; ph1.x = h2; ph1.y = h3;
    __nv_bfloat162 pl0; pl0.x = l0; pl0.y = l1;
    __nv_bfloat162 pl1; pl1.x = l2; pl1.y = l3;
    ((__nv_bfloat162*)g_wh)[idx * 2]     = ph0;
    ((__nv_bfloat162*)g_wh)[idx * 2 + 1] = ph1;
    ((__nv_bfloat162*)g_wl)[idx * 2]     = pl0;
    ((__nv_bfloat162*)g_wl)[idx * 2 + 1] = pl1;
    if (idx < 512)            g_bias[idx] = bxf[idx];
    else if (idx < 1024)      g_bias[idx] = bxb[idx - 512];
}

// ---------------------------------------------------------------------------
// mma.sync helpers (baseline PTX ISA -- compiles for plain sm_103)
// ---------------------------------------------------------------------------
__device__ __forceinline__ uint32_t smem_u32(const void* p) {
    uint32_t a;
    asm("{ .reg .u64 t; cvta.to.shared.u64 t, %1; cvt.u32.u64 %0, t; }"
        : "=r"(a) : "l"(p));
    return a;
}
__device__ __forceinline__ void ldsm4(uint32_t& r0, uint32_t& r1,
                                      uint32_t& r2, uint32_t& r3, uint32_t a) {
    asm volatile("ldmatrix.sync.aligned.m8n8.x4.shared.b16 {%0,%1,%2,%3}, [%4];"
                 : "=r"(r0), "=r"(r1), "=r"(r2), "=r"(r3) : "r"(a));
}
__device__ __forceinline__ void mma_bf16(float* c, const uint32_t* a,
                                         uint32_t b0, uint32_t b1) {
    asm volatile(
        "mma.sync.aligned.m16n8k16.row.col.f32.bf16.bf16.f32 "
        "{%0,%1,%2,%3}, {%4,%5,%6,%7}, {%8,%9}, {%0,%1,%2,%3};"
        : "+f"(c[0]), "+f"(c[1]), "+f"(c[2]), "+f"(c[3])
        : "r"(a[0]), "r"(a[1]), "r"(a[2]), "r"(a[3]), "r"(b0), "r"(b1));
}
__device__ __forceinline__ void cpasync16(uint32_t dst, const void* src) {
    asm volatile("cp.async.cg.shared.global [%0], [%1], 16;"
                 :: "r"(dst), "l"(src));
}
#define CP_COMMIT() asm volatile("cp.async.commit_group;")
#define CP_WAIT0()  asm volatile("cp.async.wait_group 0;" ::: "memory")

// ---------------------------------------------------------------------------
// xproj GEMM via mma.sync bf16x3:
// y[m][n] = sum_k x[m][k]*W[n][k] + bias[n],  M=32768, N=1024, K=512.
// CTA tile 128x128, BK=32, 8 warps (4m x 2n), warp tile 32x64.
// SMEM rows padded to 40 bf16 (80B) -> conflict-free ldmatrix.
// cp.async double-buffered stages.
// ---------------------------------------------------------------------------
#define PAD 40
#define ST_A_HI 0
#define ST_A_LO 5120
#define ST_B_HI 10240
#define ST_B_LO 15360
#define ST_SIZE 20480   /* bf16 elems per stage (40960 B) */

__global__ __launch_bounds__(256, 2) void xproj_tc_kernel(float* __restrict__ y)
{
    extern __shared__ __nv_bfloat16 sm[];
    uint32_t sbase = smem_u32(sm);

    int tid  = threadIdx.x;
    int lane = tid & 31;
    int warp = tid >> 5;
    int wm   = warp >> 1;        // 0..3  (m)
    int wn   = warp & 1;         // 0..1  (n)
    int m0 = blockIdx.y * 128;
    int n0 = blockIdx.x * 128;

    // global load mapping: idx -> row = idx>>2, k8 = (idx&3)*8
    int lrow = tid >> 2;
    int lk8  = (tid & 3) * 8;
    int lrow2 = (tid + 256) >> 2;
    int lk82  = ((tid + 256) & 3) * 8;

    // smem element offsets for cp.async stores
    uint32_t soA1 = (uint32_t)(lrow  * PAD + lk8);
    uint32_t soA2 = (uint32_t)(lrow2 * PAD + lk82);

    // per-thread ldmatrix offsets (bf16 elems)
    uint32_t a_off = (uint32_t)((wm * 32 + (lane & 15)) * PAD + (lane >> 4) * 8);
    uint32_t b_off = (uint32_t)((wn * 64 + (lane >> 4) * 8 + (lane & 7)) * PAD +
                                ((lane >> 3) & 1) * 8);

    float acc[2][8][4];
#pragma unroll
    for (int mf = 0; mf < 2; mf++)
#pragma unroll
        for (int nf = 0; nf < 8; nf++)
#pragma unroll
            for (int q = 0; q < 4; q++) acc[mf][nf][q] = 0.f;

    // prologue: issue chunk 0 into stage 0
    {
        const __nv_bfloat16* gah = &g_xh[(size_t)(m0 + lrow) * 512 + lk8];
        const __nv_bfloat16* gal = &g_xl[(size_t)(m0 + lrow) * 512 + lk8];
        const __nv_bfloat16* gbh = &g_wh[(size_t)(n0 + lrow) * 512 + lk8];
        const __nv_bfloat16* gbl = &g_wl[(size_t)(n0 + lrow) * 512 + lk8];
        const __nv_bfloat16* gah2 = &g_xh[(size_t)(m0 + lrow2) * 512 + lk82];
        const __nv_bfloat16* gal2 = &g_xl[(size_t)(m0 + lrow2) * 512 + lk82];
        const __nv_bfloat16* gbh2 = &g_wh[(size_t)(n0 + lrow2) * 512 + lk82];
        const __nv_bfloat16* gbl2 = &g_wl[(size_t)(n0 + lrow2) * 512 + lk82];
        cpasync16(sbase + (ST_A_HI + soA1) * 2, gah);
        cpasync16(sbase + (ST_A_HI + soA2) * 2, gah2);
        cpasync16(sbase + (ST_A_LO + soA1) * 2, gal);
        cpasync16(sbase + (ST_A_LO + soA2) * 2, gal2);
        cpasync16(sbase + (ST_B_HI + soA1) * 2, gbh);
        cpasync16(sbase + (ST_B_HI + soA2) * 2, gbh2);
        cpasync16(sbase + (ST_B_LO + soA1) * 2, gbl);
        cpasync16(sbase + (ST_B_LO + soA2) * 2, gbl2);
        CP_COMMIT();
    }
    CP_WAIT0();
    __syncthreads();

    for (int c = 0; c < 16; ++c) {
        uint32_t stage = (uint32_t)(c & 1) * ST_SIZE;
        // issue chunk c+1 into the other stage
        if (c < 15) {
            int kc = (c + 1) * 32;
            uint32_t st2 = (uint32_t)((c + 1) & 1) * ST_SIZE;
            cpasync16(sbase + (st2 + ST_A_HI + soA1) * 2,
                      &g_xh[(size_t)(m0 + lrow) * 512 + kc + lk8]);
            cpasync16(sbase + (st2 + ST_A_HI + soA2) * 2,
                      &g_xh[(size_t)(m0 + lrow2) * 512 + kc + lk82]);
            cpasync16(sbase + (st2 + ST_A_LO + soA1) * 2,
                      &g_xl[(size_t)(m0 + lrow) * 512 + kc + lk8]);
            cpasync16(sbase + (st2 + ST_A_LO + soA2) * 2,
                      &g_xl[(size_t)(m0 + lrow2) * 512 + kc + lk82]);
            cpasync16(sbase + (st2 + ST_B_HI + soA1) * 2,
                      &g_wh[(size_t)(n0 + lrow) * 512 + kc + lk8]);
            cpasync16(sbase + (st2 + ST_B_HI + soA2) * 2,
                      &g_wh[(size_t)(n0 + lrow2) * 512 + kc + lk82]);
            cpasync16(sbase + (st2 + ST_B_LO + soA1) * 2,
                      &g_wl[(size_t)(n0 + lrow) * 512 + kc + lk8]);
            cpasync16(sbase + (st2 + ST_B_LO + soA2) * 2,
                      &g_wl[(size_t)(n0 + lrow2) * 512 + kc + lk82]);
            CP_COMMIT();
        }

        // compute on current stage: 2 k-steps of 16
#pragma unroll
        for (int ks = 0; ks < 2; ++ks) {
            uint32_t k0 = (uint32_t)ks * 16;
            uint32_t ah[2][4], al[2][4], bq[4][4];
            // A hi + lo frags (2 m-frags each)
#pragma unroll
            for (int mf = 0; mf < 2; mf++) {
                uint32_t ad = sbase +
                    (stage + ST_A_HI + a_off + (uint32_t)mf * 16 * PAD + k0) * 2;
                ldsm4(ah[mf][0], ah[mf][1], ah[mf][2], ah[mf][3], ad);
                uint32_t ad2 = sbase +
                    (stage + ST_A_LO + a_off + (uint32_t)mf * 16 * PAD + k0) * 2;
                ldsm4(al[mf][0], al[mf][1], al[mf][2], al[mf][3], ad2);
            }
            // B hi frags: 4 x4 groups, each covers 2 n-frags
#pragma unroll
            for (int g = 0; g < 4; g++) {
                uint32_t bd = sbase +
                    (stage + ST_B_HI + b_off + (uint32_t)g * 16 * PAD + k0) * 2;
                ldsm4(bq[g][0], bq[g][1], bq[g][2], bq[g][3], bd);
            }
            // Ahi*Bhi + Alo*Bhi
#pragma unroll
            for (int mf = 0; mf < 2; mf++)
#pragma unroll
                for (int g = 0; g < 4; g++) {
                    mma_bf16(acc[mf][g * 2],     ah[mf], bq[g][0], bq[g][1]);
                    mma_bf16(acc[mf][g * 2 + 1], ah[mf], bq[g][2], bq[g][3]);
                    mma_bf16(acc[mf][g * 2],     al[mf], bq[g][0], bq[g][1]);
                    mma_bf16(acc[mf][g * 2 + 1], al[mf], bq[g][2], bq[g][3]);
                }
            // B lo frags (overwrite bq)
#pragma unroll
            for (int g = 0; g < 4; g++) {
                uint32_t bd = sbase +
                    (stage + ST_B_LO + b_off + (uint32_t)g * 16 * PAD + k0) * 2;
                ldsm4(bq[g][0], bq[g][1], bq[g][2], bq[g][3], bd);
            }
            // Ahi*Blo
#pragma unroll
            for (int mf = 0; mf < 2; mf++)
#pragma unroll
                for (int g = 0; g < 4; g++) {
                    mma_bf16(acc[mf][g * 2],     ah[mf], bq[g][0], bq[g][1]);
                    mma_bf16(acc[mf][g * 2 + 1], ah[mf], bq[g][2], bq[g][3]);
                }
        }
        CP_WAIT0();
        __syncthreads();
    }

    // epilogue: write y + bias. acc element (mf,nf,q):
    // row = m0 + wm*32 + mf*16 + lane/4 + (q>=2 ? 8 : 0)
    // col = n0 + wn*64 + nf*8 + (lane%4)*2 + (q&1)
    int rbase = m0 + wm * 32 + (lane >> 2);
    int cbase = n0 + wn * 64 + (lane & 3) * 2;
#pragma unroll
    for (int mf = 0; mf < 2; mf++) {
#pragma unroll
        for (int nf = 0; nf < 8; nf++) {
            int col = cbase + nf * 8;
            float2 bias2 = *(const float2*)&g_bias[col];
            int r0 = rbase + mf * 16;
            float2 v0, v1;
            v0.x = acc[mf][nf][0] + bias2.x;
            v0.y = acc[mf][nf][1] + bias2.y;
            v1.x = acc[mf][nf][2] + bias2.x;
            v1.y = acc[mf][nf][3] + bias2.y;
            *(float2*)&y[(size_t)r0 * 1024 + col]       = v0;
            *(float2*)&y[(size_t)(r0 + 8) * 1024 + col] = v1;
        }
    }
}

// ---------------------------------------------------------------------------
// Phase 2: persistent recurrence kernel (unchanged from best-known 3398us).
// ---------------------------------------------------------------------------
__global__ __launch_bounds__(256) void rnn_kernel(
    const float* __restrict__ Whf, const float* __restrict__ Whb,
    float* __restrict__ y, float* __restrict__ out_hT)
{
    extern __shared__ float smemf[];
    float* sh_wt = smemf;                       // [512][8] transposed Wh slice
    float* sh_h  = smemf + 4096;                // 8 warps x 2 x [8][68]
    float* red   = sh_h + 8 * 2 * 8 * 68;       // [8][520] partials
    float* sxp   = red + 8 * 520;               // [512] xp in / h out

    int tid  = threadIdx.x;
    int bx   = blockIdx.x;
    int dir  = bx >> 6;
    int jblk = (bx & 63) * 8;
    const float* Wh = dir ? Whb : Whf;

    for (int r = 0; r < 16; ++r) {
        int idx = tid + 256 * r;
        int j = idx >> 9, k = idx & 511;
        sh_wt[k * 8 + j] = Wh[(jblk + j) * Hh + k];
    }
    __syncthreads();

    int sl = tid >> 5;
    int sp = tid & 31;
    int b0 = (sp & 15) * 4;
    int j0 = (sp >> 4) * 4;
    int warpk0 = sl * 64;
    float* wbuf = sh_h + sl * (2 * 8 * 68);
    int yhalf = dir * Hh;

    int jy = tid & 7;
    int by = tid >> 3;

    int o1 = tid, o2 = tid + 256;
    int jo1 = o1 >> 6, bo1 = o1 & 63;
    int jo2 = o2 >> 6, bo2 = o2 & 63;

    for (int s = 0; s < Tt; ++s) {
        int t = dir ? (Tt - 1 - s) : s;
        const float* hsrc = g_h[dir][s & 1];
        float* hdst       = g_h[dir][(s + 1) & 1];

        size_t ycol = (size_t)t * (2 * Hh) + yhalf + jblk + jy;
        float xpa = y[(size_t)by * (Tt * 2 * Hh) + ycol];
        float xpb = y[(size_t)(by + 32) * (Tt * 2 * Hh) + ycol];

        float acc[4][4];
#pragma unroll
        for (int i = 0; i < 4; i++)
#pragma unroll
            for (int j = 0; j < 4; j++) acc[i][j] = 0.f;

        const float* gsrc = hsrc + warpk0 * Bsz;
        float4 pf[4];
#pragma unroll
        for (int r = 0; r < 4; ++r)
            pf[r] = __ldcg((const float4*)&gsrc[(sp + 32 * r) * 4]);
        int cur = 0;
        for (int c = 0; c < 8; ++c) {
            float* buf = wbuf + cur * (8 * 68);
#pragma unroll
            for (int r = 0; r < 4; ++r) {
                int idx = sp + 32 * r;
                int kk = idx >> 4, b4 = idx & 15;
                *(float4*)&buf[kk * 68 + b4 * 4] = pf[r];
            }
            if (c < 7) {
#pragma unroll
                for (int r = 0; r < 4; ++r)
                    pf[r] = __ldcg((const float4*)
                                   &gsrc[(c + 1) * 512 + (sp + 32 * r) * 4]);
            }
            __syncwarp();
            int kb = warpk0 + c * 8;
#pragma unroll
            for (int u = 0; u < 8; ++u) {
                float4 h4 = *(const float4*)&buf[u * 68 + b0];
                float4 w4 = *(const float4*)&sh_wt[(kb + u) * 8 + j0];
                float hv[4] = {h4.x, h4.y, h4.z, h4.w};
                float wv[4] = {w4.x, w4.y, w4.z, w4.w};
#pragma unroll
                for (int ji = 0; ji < 4; ji++)
#pragma unroll
                    for (int bi = 0; bi < 4; bi++)
                        acc[ji][bi] = fmaf(wv[ji], hv[bi], acc[ji][bi]);
            }
            cur ^= 1;
        }

        sxp[jy * 64 + by]      = xpa;
        sxp[jy * 64 + by + 32] = xpb;
#pragma unroll
        for (int ji = 0; ji < 4; ji++) {
            float4 v;
            v.x = acc[ji][0]; v.y = acc[ji][1];
            v.z = acc[ji][2]; v.w = acc[ji][3];
            *(float4*)&red[sl * 520 + (j0 + ji) * 64 + b0] = v;
        }
        __syncthreads();

        float v1 = sxp[o1], v2 = sxp[o2];
#pragma unroll
        for (int q = 0; q < 8; ++q) {
            v1 += red[q * 520 + o1];
            v2 += red[q * 520 + o2];
        }
        v1 = tanhf(v1);
        v2 = tanhf(v2);
        hdst[(jblk + jo1) * Bsz + bo1] = v1;
        hdst[(jblk + jo2) * Bsz + bo2] = v2;
        sxp[o1] = v1;
        sxp[o2] = v2;
        if (s == Tt - 1) {
            float* ht = out_hT + (size_t)dir * (Bsz * Hh);
            ht[bo1 * Hh + jblk + jo1] = v1;
            ht[bo2 * Hh + jblk + jo2] = v2;
        }

        __threadfence();
        __syncthreads();
        if (tid == 0) atomicAdd(&g_cnt[dir][s], 1);

        y[(size_t)by * (Tt * 2 * Hh) + ycol]        = sxp[jy * 64 + by];
        y[(size_t)(by + 32) * (Tt * 2 * Hh) + ycol] = sxp[jy * 64 + by + 32];

        if (s < Tt - 1) {
            if (tid == 0) {
                int v;
                do {
                    asm volatile("ld.acquire.gpu.global.b32 %0, [%1];"
                                 : "=r"(v) : "l"(&g_cnt[dir][s]) : "memory");
                } while (v < 64);
            }
            __syncthreads();
        } else {
            __syncthreads();
        }
    }
}

// ---------------------------------------------------------------------------
extern "C" void kernel_launch(void* const* d_in, const int* in_sizes, int n_in,
                              void* d_out, int out_size) {
    const float* x    = (const float*)d_in[0];
    const float* h0_f = (const float*)d_in[1];
    const float* h0_b = (const float*)d_in[2];
    const float* Wxf_w = (const float*)d_in[3];
    const float* Wxf_b = (const float*)d_in[4];
    const float* Whf_w = (const float*)d_in[5];
    const float* Wxb_w = (const float*)d_in[6];
    const float* Wxb_b = (const float*)d_in[7];
    const float* Whb_w = (const float*)d_in[8];

    float* y  = (float*)d_out;
    float* hT = y + (size_t)Bsz * Tt * 2 * Hh;

    cudaFuncSetAttribute(rnn_kernel,
                         cudaFuncAttributeMaxDynamicSharedMemorySize,
                         72 * 1024);
    cudaFuncSetAttribute(xproj_tc_kernel,
                         cudaFuncAttributeMaxDynamicSharedMemorySize,
                         2 * ST_SIZE * 2);

    init_kernel<<<64, 512>>>(h0_f, h0_b);
    split_x_kernel<<<16384, 256>>>(x);
    split_w_kernel<<<512, 256>>>(Wxf_w, Wxb_w, Wxf_b, Wxb_b);

    dim3 grid(1024 / 128, 32768 / 128);
    xproj_tc_kernel<<<grid, 256, 2 * ST_SIZE * 2>>>(y);

    rnn_kernel<<<128, 256, 72 * 1024>>>(Whf_w, Whb_w, y, hT);
    (void)in_sizes; (void)n_in; (void)out_size;
}

// round 16
// speedup vs baseline: 1.5793x; 1.0634x over previous
#include <cuda_runtime.h>
#include <cuda_bf16.h>
#include <cstdint>

#define Bsz 64
#define Tt  512
#define Ii  512
#define Hh  512

// hidden state, double buffered, bf16 hi/lo, b-major: [dir][par][hi/lo][b*512+k]
__device__ __nv_bfloat16 g_hbf[2][2][2][Hh * Bsz];
// per-step arrival counters per direction
__device__ int g_cnt[2][Tt];

// bf16 split operands for the xproj GEMM
__device__ __nv_bfloat16 g_xh[32768 * 512];
__device__ __nv_bfloat16 g_xl[32768 * 512];
__device__ __nv_bfloat16 g_wh[1024 * 512];
__device__ __nv_bfloat16 g_wl[1024 * 512];
__device__ float g_bias[1024];

// ---------------------------------------------------------------------------
__device__ __forceinline__ uint32_t pack_bf2(float a, float b) {
    __nv_bfloat162 t;
    t.x = __float2bfloat16(a);
    t.y = __float2bfloat16(b);
    uint32_t u;
    __builtin_memcpy(&u, &t, 4);
    return u;
}

// ---------------------------------------------------------------------------
// init: zero counters, stage h0 as bf16 hi/lo (b-major)
// ---------------------------------------------------------------------------
__global__ void init_kernel(const float* __restrict__ h0f,
                            const float* __restrict__ h0b) {
    int idx = blockIdx.x * blockDim.x + threadIdx.x;   // 0..32767
    float vf = h0f[idx];
    float vb = h0b[idx];
    __nv_bfloat16 hf = __float2bfloat16(vf);
    __nv_bfloat16 hb = __float2bfloat16(vb);
    g_hbf[0][0][0][idx] = hf;
    g_hbf[0][0][1][idx] = __float2bfloat16(vf - __bfloat162float(hf));
    g_hbf[1][0][0][idx] = hb;
    g_hbf[1][0][1][idx] = __float2bfloat16(vb - __bfloat162float(hb));
    if (idx < 2 * Tt) ((int*)g_cnt)[idx] = 0;
}

// ---------------------------------------------------------------------------
// split fp32 -> bf16 hi/lo
// ---------------------------------------------------------------------------
__global__ __launch_bounds__(256) void split_x_kernel(const float* __restrict__ x) {
    int idx = blockIdx.x * blockDim.x + threadIdx.x;   // 0..4194303
    float4 v = ((const float4*)x)[idx];
    __nv_bfloat16 h0 = __float2bfloat16(v.x);
    __nv_bfloat16 h1 = __float2bfloat16(v.y);
    __nv_bfloat16 h2 = __float2bfloat16(v.z);
    __nv_bfloat16 h3 = __float2bfloat16(v.w);
    __nv_bfloat16 l0 = __float2bfloat16(v.x - __bfloat162float(h0));
    __nv_bfloat16 l1 = __float2bfloat16(v.y - __bfloat162float(h1));
    __nv_bfloat16 l2 = __float2bfloat16(v.z - __bfloat162float(h2));
    __nv_bfloat16 l3 = __float2bfloat16(v.w - __bfloat162float(h3));
    __nv_bfloat162 ph0; ph0.x = h0; ph0.y = h1;
    __nv_bfloat162 ph1; ph1.x = h2; ph1.y = h3;
    __nv_bfloat162 pl0; pl0.x = l0; pl0.y = l1;
    __nv_bfloat162 pl1; pl1.x = l2; pl1.y = l3;
    ((__nv_bfloat162*)g_xh)[idx * 2]     = ph0;
    ((__nv_bfloat162*)g_xh)[idx * 2 + 1] = ph1;
    ((__nv_bfloat162*)g_xl)[idx * 2]     = pl0;
    ((__nv_bfloat162*)g_xl)[idx * 2 + 1] = pl1;
}

__global__ __launch_bounds__(256) void split_w_kernel(
    const float* __restrict__ Wxf, const float* __restrict__ Wxb,
    const float* __restrict__ bxf, const float* __restrict__ bxb) {
    int idx = blockIdx.x * blockDim.x + threadIdx.x;   // 0..131071
    int j = idx >> 7;               // 0..1023
    int c4 = (idx & 127) * 4;
    const float* src = (j < 512) ? &Wxf[j * 512 + c4]
                                 : &Wxb[(j - 512) * 512 + c4];
    float4 v = *(const float4*)src;
    __nv_bfloat16 h0 = __float2bfloat16(v.x);
    __nv_bfloat16 h1 = __float2bfloat16(v.y);
    __nv_bfloat16 h2 = __float2bfloat16(v.z);
    __nv_bfloat16 h3 = __float2bfloat16(v.w);
    __nv_bfloat16 l0 = __float2bfloat16(v.x - __bfloat162float(h0));
    __nv_bfloat16 l1 = __float2bfloat16(v.y - __bfloat162float(h1));
    __nv_bfloat16 l2 = __float2bfloat16(v.z - __bfloat162float(h2));
    __nv_bfloat16 l3 = __float2bfloat16(v.w - __bfloat162float(h3));
    __nv_bfloat162 ph0; ph0.x = h0; ph0.y = h1;
    __nv_bfloat162 ph1; ph1.x = h2; ph1.y = h3;
    __nv_bfloat162 pl0; pl0.x = l0; pl0.y = l1;
    __nv_bfloat162 pl1; pl1.x = l2; pl1.y = l3;
    ((__nv_bfloat162*)g_wh)[idx * 2]     = ph0;
    ((__nv_bfloat162*)g_wh)[idx * 2 + 1] = ph1;
    ((__nv_bfloat162*)g_wl)[idx * 2]     = pl0;
    ((__nv_bfloat162*)g_wl)[idx * 2 + 1] = pl1;
    if (idx < 512)            g_bias[idx] = bxf[idx];
    else if (idx < 1024)      g_bias[idx] = bxb[idx - 512];
}

// ---------------------------------------------------------------------------
// mma.sync helpers
// ---------------------------------------------------------------------------
__device__ __forceinline__ uint32_t smem_u32(const void* p) {
    uint32_t a;
    asm("{ .reg .u64 t; cvta.to.shared.u64 t, %1; cvt.u32.u64 %0, t; }"
        : "=r"(a) : "l"(p));
    return a;
}
__device__ __forceinline__ void ldsm4(uint32_t& r0, uint32_t& r1,
                                      uint32_t& r2, uint32_t& r3, uint32_t a) {
    asm volatile("ldmatrix.sync.aligned.m8n8.x4.shared.b16 {%0,%1,%2,%3}, [%4];"
                 : "=r"(r0), "=r"(r1), "=r"(r2), "=r"(r3) : "r"(a));
}
__device__ __forceinline__ void mma_bf16(float* c, const uint32_t* a,
                                         uint32_t b0, uint32_t b1) {
    asm volatile(
        "mma.sync.aligned.m16n8k16.row.col.f32.bf16.bf16.f32 "
        "{%0,%1,%2,%3}, {%4,%5,%6,%7}, {%8,%9}, {%0,%1,%2,%3};"
        : "+f"(c[0]), "+f"(c[1]), "+f"(c[2]), "+f"(c[3])
        : "r"(a[0]), "r"(a[1]), "r"(a[2]), "r"(a[3]), "r"(b0), "r"(b1));
}
__device__ __forceinline__ void cpasync16(uint32_t dst, const void* src) {
    asm volatile("cp.async.cg.shared.global [%0], [%1], 16;"
                 :: "r"(dst), "l"(src));
}
#define CP_COMMIT() asm volatile("cp.async.commit_group;")
#define CP_WAIT0()  asm volatile("cp.async.wait_group 0;" ::: "memory")

// ---------------------------------------------------------------------------
// xproj GEMM via mma.sync bf16x3 (unchanged from 282us best).
// ---------------------------------------------------------------------------
#define PAD 40
#define ST_A_HI 0
#define ST_A_LO 5120
#define ST_B_HI 10240
#define ST_B_LO 15360
#define ST_SIZE 20480

__global__ __launch_bounds__(256, 2) void xproj_tc_kernel(float* __restrict__ y)
{
    extern __shared__ __nv_bfloat16 sm[];
    uint32_t sbase = smem_u32(sm);

    int tid  = threadIdx.x;
    int lane = tid & 31;
    int warp = tid >> 5;
    int wm   = warp >> 1;
    int wn   = warp & 1;
    int m0 = blockIdx.y * 128;
    int n0 = blockIdx.x * 128;

    int lrow = tid >> 2;
    int lk8  = (tid & 3) * 8;
    int lrow2 = (tid + 256) >> 2;
    int lk82  = ((tid + 256) & 3) * 8;

    uint32_t soA1 = (uint32_t)(lrow  * PAD + lk8);
    uint32_t soA2 = (uint32_t)(lrow2 * PAD + lk82);

    uint32_t a_off = (uint32_t)((wm * 32 + (lane & 15)) * PAD + (lane >> 4) * 8);
    uint32_t b_off = (uint32_t)((wn * 64 + (lane >> 4) * 8 + (lane & 7)) * PAD +
                                ((lane >> 3) & 1) * 8);

    float acc[2][8][4];
#pragma unroll
    for (int mf = 0; mf < 2; mf++)
#pragma unroll
        for (int nf = 0; nf < 8; nf++)
#pragma unroll
            for (int q = 0; q < 4; q++) acc[mf][nf][q] = 0.f;

    {
        cpasync16(sbase + (ST_A_HI + soA1) * 2, &g_xh[(size_t)(m0 + lrow) * 512 + lk8]);
        cpasync16(sbase + (ST_A_HI + soA2) * 2, &g_xh[(size_t)(m0 + lrow2) * 512 + lk82]);
        cpasync16(sbase + (ST_A_LO + soA1) * 2, &g_xl[(size_t)(m0 + lrow) * 512 + lk8]);
        cpasync16(sbase + (ST_A_LO + soA2) * 2, &g_xl[(size_t)(m0 + lrow2) * 512 + lk82]);
        cpasync16(sbase + (ST_B_HI + soA1) * 2, &g_wh[(size_t)(n0 + lrow) * 512 + lk8]);
        cpasync16(sbase + (ST_B_HI + soA2) * 2, &g_wh[(size_t)(n0 + lrow2) * 512 + lk82]);
        cpasync16(sbase + (ST_B_LO + soA1) * 2, &g_wl[(size_t)(n0 + lrow) * 512 + lk8]);
        cpasync16(sbase + (ST_B_LO + soA2) * 2, &g_wl[(size_t)(n0 + lrow2) * 512 + lk82]);
        CP_COMMIT();
    }
    CP_WAIT0();
    __syncthreads();

    for (int c = 0; c < 16; ++c) {
        uint32_t stage = (uint32_t)(c & 1) * ST_SIZE;
        if (c < 15) {
            int kc = (c + 1) * 32;
            uint32_t st2 = (uint32_t)((c + 1) & 1) * ST_SIZE;
            cpasync16(sbase + (st2 + ST_A_HI + soA1) * 2,
                      &g_xh[(size_t)(m0 + lrow) * 512 + kc + lk8]);
            cpasync16(sbase + (st2 + ST_A_HI + soA2) * 2,
                      &g_xh[(size_t)(m0 + lrow2) * 512 + kc + lk82]);
            cpasync16(sbase + (st2 + ST_A_LO + soA1) * 2,
                      &g_xl[(size_t)(m0 + lrow) * 512 + kc + lk8]);
            cpasync16(sbase + (st2 + ST_A_LO + soA2) * 2,
                      &g_xl[(size_t)(m0 + lrow2) * 512 + kc + lk82]);
            cpasync16(sbase + (st2 + ST_B_HI + soA1) * 2,
                      &g_wh[(size_t)(n0 + lrow) * 512 + kc + lk8]);
            cpasync16(sbase + (st2 + ST_B_HI + soA2) * 2,
                      &g_wh[(size_t)(n0 + lrow2) * 512 + kc + lk82]);
            cpasync16(sbase + (st2 + ST_B_LO + soA1) * 2,
                      &g_wl[(size_t)(n0 + lrow) * 512 + kc + lk8]);
            cpasync16(sbase + (st2 + ST_B_LO + soA2) * 2,
                      &g_wl[(size_t)(n0 + lrow2) * 512 + kc + lk82]);
            CP_COMMIT();
        }

#pragma unroll
        for (int ks = 0; ks < 2; ++ks) {
            uint32_t k0 = (uint32_t)ks * 16;
            uint32_t ah[2][4], al[2][4], bq[4][4];
#pragma unroll
            for (int mf = 0; mf < 2; mf++) {
                uint32_t ad = sbase +
                    (stage + ST_A_HI + a_off + (uint32_t)mf * 16 * PAD + k0) * 2;
                ldsm4(ah[mf][0], ah[mf][1], ah[mf][2], ah[mf][3], ad);
                uint32_t ad2 = sbase +
                    (stage + ST_A_LO + a_off + (uint32_t)mf * 16 * PAD + k0) * 2;
                ldsm4(al[mf][0], al[mf][1], al[mf][2], al[mf][3], ad2);
            }
#pragma unroll
            for (int g = 0; g < 4; g++) {
                uint32_t bd = sbase +
                    (stage + ST_B_HI + b_off + (uint32_t)g * 16 * PAD + k0) * 2;
                ldsm4(bq[g][0], bq[g][1], bq[g][2], bq[g][3], bd);
            }
#pragma unroll
            for (int mf = 0; mf < 2; mf++)
#pragma unroll
                for (int g = 0; g < 4; g++) {
                    mma_bf16(acc[mf][g * 2],     ah[mf], bq[g][0], bq[g][1]);
                    mma_bf16(acc[mf][g * 2 + 1], ah[mf], bq[g][2], bq[g][3]);
                    mma_bf16(acc[mf][g * 2],     al[mf], bq[g][0], bq[g][1]);
                    mma_bf16(acc[mf][g * 2 + 1], al[mf], bq[g][2], bq[g][3]);
                }
#pragma unroll
            for (int g = 0; g < 4; g++) {
                uint32_t bd = sbase +
                    (stage + ST_B_LO + b_off + (uint32_t)g * 16 * PAD + k0) * 2;
                ldsm4(bq[g][0], bq[g][1], bq[g][2], bq[g][3], bd);
            }
#pragma unroll
            for (int mf = 0; mf < 2; mf++)
#pragma unroll
                for (int g = 0; g < 4; g++) {
                    mma_bf16(acc[mf][g * 2],     ah[mf], bq[g][0], bq[g][1]);
                    mma_bf16(acc[mf][g * 2 + 1], ah[mf], bq[g][2], bq[g][3]);
                }
        }
        CP_WAIT0();
        __syncthreads();
    }

    int rbase = m0 + wm * 32 + (lane >> 2);
    int cbase = n0 + wn * 64 + (lane & 3) * 2;
#pragma unroll
    for (int mf = 0; mf < 2; mf++) {
#pragma unroll
        for (int nf = 0; nf < 8; nf++) {
            int col = cbase + nf * 8;
            float2 bias2 = *(const float2*)&g_bias[col];
            int r0 = rbase + mf * 16;
            float2 v0, v1;
            v0.x = acc[mf][nf][0] + bias2.x;
            v0.y = acc[mf][nf][1] + bias2.y;
            v1.x = acc[mf][nf][2] + bias2.x;
            v1.y = acc[mf][nf][3] + bias2.y;
            *(float2*)&y[(size_t)r0 * 1024 + col]       = v0;
            *(float2*)&y[(size_t)(r0 + 8) * 1024 + col] = v1;
        }
    }
}

// ---------------------------------------------------------------------------
// Phase 2: persistent recurrence via mma.sync bf16x3.
// 128 CTAs (64/dir), each owns 8 j-cols. 8 warps = k-slices of 64.
// W slice lives in registers (loaded once). h staged per step via cp.async
// into SMEM (bf16 hi/lo, b-major rows padded to 520).
// ---------------------------------------------------------------------------
#define HPAD 520

__global__ __launch_bounds__(256) void rnn_tc_kernel(
    const float* __restrict__ Whf, const float* __restrict__ Whb,
    float* __restrict__ y, float* __restrict__ out_hT)
{
    extern __shared__ char smemc[];
    // sh_hi: [64][520] bf16 ; sh_lo: same ; red: [8][512] float
    __nv_bfloat16* sh_hi = (__nv_bfloat16*)smemc;
    __nv_bfloat16* sh_lo = sh_hi + 64 * HPAD;
    float* red = (float*)(smemc + 2 * 64 * HPAD * 2);
    uint32_t s_hi = smem_u32(sh_hi);
    uint32_t s_lo = smem_u32(sh_lo);

    int tid  = threadIdx.x;
    int lane = tid & 31;
    int w    = tid >> 5;
    int bx   = blockIdx.x;
    int dir  = bx >> 6;
    int jblk = (bx & 63) * 8;
    const float* Wh = dir ? Whb : Whf;
    int yhalf = dir * Hh;

    // --- load W slice into registers (once): B-frags for m16n8k16 ---
    // warp w covers k in [w*64, w*64+64): 4 k-frags of 16.
    uint32_t whi[4][2], wlo[4][2];
    {
        int j = jblk + (lane >> 2);
#pragma unroll
        for (int kf = 0; kf < 4; kf++) {
            int kb = w * 64 + kf * 16 + (lane & 3) * 2;
            float a0 = Wh[j * Hh + kb];
            float a1 = Wh[j * Hh + kb + 1];
            float a2 = Wh[j * Hh + kb + 8];
            float a3 = Wh[j * Hh + kb + 9];
            float h0 = __bfloat162float(__float2bfloat16(a0));
            float h1 = __bfloat162float(__float2bfloat16(a1));
            float h2 = __bfloat162float(__float2bfloat16(a2));
            float h3 = __bfloat162float(__float2bfloat16(a3));
            whi[kf][0] = pack_bf2(a0, a1);
            whi[kf][1] = pack_bf2(a2, a3);
            wlo[kf][0] = pack_bf2(a0 - h0, a1 - h1);
            wlo[kf][1] = pack_bf2(a2 - h2, a3 - h3);
        }
    }

    // y/xp mapping: thread tid -> (b = tid>>3, j = tid&7); second (b+32, j)
    int jy = tid & 7;
    int by = tid >> 3;

    // A-frag ldmatrix offsets (elems): row mf*16+(lane&15), col w*64+kf*16+(lane>>4)*8
    uint32_t a_base = (uint32_t)((lane & 15) * HPAD + w * 64 + (lane >> 4) * 8);

    for (int s = 0; s < Tt; ++s) {
        int t = dir ? (Tt - 1 - s) : s;
        const __nv_bfloat16* hs_hi = g_hbf[dir][s & 1][0];
        const __nv_bfloat16* hs_lo = g_hbf[dir][s & 1][1];
        __nv_bfloat16* hd_hi = g_hbf[dir][(s + 1) & 1][0];
        __nv_bfloat16* hd_lo = g_hbf[dir][(s + 1) & 1][1];

        // stage h (hi+lo) into smem: 64 rows x 1024B each, 16B chunks
#pragma unroll
        for (int it = 0; it < 16; ++it) {
            int cid = tid + it * 256;          // 0..4095
            int row = cid >> 6;
            int ch  = (cid & 63) * 8;          // elem offset
            cpasync16(s_hi + (uint32_t)(row * HPAD + ch) * 2, &hs_hi[row * 512 + ch]);
            cpasync16(s_lo + (uint32_t)(row * HPAD + ch) * 2, &hs_lo[row * 512 + ch]);
        }
        CP_COMMIT();

        // xp loads overlap the cp.async
        size_t ycol = (size_t)t * (2 * Hh) + yhalf + jblk + jy;
        float xpa = y[(size_t)by * (Tt * 2 * Hh) + ycol];
        float xpb = y[(size_t)(by + 32) * (Tt * 2 * Hh) + ycol];

        CP_WAIT0();
        __syncthreads();

        // compute: 4 m-frags x 4 k-frags, bf16x3
        float acc[4][4];
#pragma unroll
        for (int mf = 0; mf < 4; mf++)
#pragma unroll
            for (int q = 0; q < 4; q++) acc[mf][q] = 0.f;

#pragma unroll
        for (int kf = 0; kf < 4; kf++) {
            uint32_t ah[4][4], al[4][4];
#pragma unroll
            for (int mf = 0; mf < 4; mf++) {
                uint32_t off = (a_base + (uint32_t)(mf * 16) * HPAD +
                                (uint32_t)kf * 16) * 2;
                ldsm4(ah[mf][0], ah[mf][1], ah[mf][2], ah[mf][3], s_hi + off);
                ldsm4(al[mf][0], al[mf][1], al[mf][2], al[mf][3], s_lo + off);
            }
#pragma unroll
            for (int mf = 0; mf < 4; mf++) {
                mma_bf16(acc[mf], ah[mf], whi[kf][0], whi[kf][1]);
                mma_bf16(acc[mf], al[mf], whi[kf][0], whi[kf][1]);
                mma_bf16(acc[mf], ah[mf], wlo[kf][0], wlo[kf][1]);
            }
        }

        // partials to red: acc (mf,{c0..c3}) -> row mf*16+lane/4 (+8), col (lane%4)*2
        {
            float* rw = red + w * 512;
            int rb = (lane >> 2);
            int cb = (lane & 3) * 2;
#pragma unroll
            for (int mf = 0; mf < 4; mf++) {
                float2 v0; v0.x = acc[mf][0]; v0.y = acc[mf][1];
                float2 v1; v1.x = acc[mf][2]; v1.y = acc[mf][3];
                *(float2*)&rw[(mf * 16 + rb) * 8 + cb]     = v0;
                *(float2*)&rw[(mf * 16 + rb + 8) * 8 + cb] = v1;
            }
        }
        __syncthreads();

        // gather + tanh; thread tid owns outputs o=tid and o=tid+256 (b-major)
        float v1 = xpa, v2 = xpb;
#pragma unroll
        for (int q = 0; q < 8; ++q) {
            v1 += red[q * 512 + tid];
            v2 += red[q * 512 + tid + 256];
        }
        v1 = tanhf(v1);
        v2 = tanhf(v2);

        // write h (bf16 hi/lo), y
        {
            int g1 = by * 512 + jblk + jy;
            int g2 = (by + 32) * 512 + jblk + jy;
            __nv_bfloat16 h1b = __float2bfloat16(v1);
            __nv_bfloat16 h2b = __float2bfloat16(v2);
            hd_hi[g1] = h1b;
            hd_lo[g1] = __float2bfloat16(v1 - __bfloat162float(h1b));
            hd_hi[g2] = h2b;
            hd_lo[g2] = __float2bfloat16(v2 - __bfloat162float(h2b));
        }
        y[(size_t)by * (Tt * 2 * Hh) + ycol]        = v1;
        y[(size_t)(by + 32) * (Tt * 2 * Hh) + ycol] = v2;
        if (s == Tt - 1) {
            float* ht = out_hT + (size_t)dir * (Bsz * Hh);
            ht[by * Hh + jblk + jy]        = v1;
            ht[(by + 32) * Hh + jblk + jy] = v2;
        }

        __threadfence();
        __syncthreads();
        if (tid == 0) atomicAdd(&g_cnt[dir][s], 1);

        if (s < Tt - 1) {
            if (tid == 0) {
                int v;
                do {
                    asm volatile("ld.acquire.gpu.global.b32 %0, [%1];"
                                 : "=r"(v) : "l"(&g_cnt[dir][s]) : "memory");
                } while (v < 64);
            }
            __syncthreads();
        }
    }
}

// ---------------------------------------------------------------------------
extern "C" void kernel_launch(void* const* d_in, const int* in_sizes, int n_in,
                              void* d_out, int out_size) {
    const float* x    = (const float*)d_in[0];
    const float* h0_f = (const float*)d_in[1];
    const float* h0_b = (const float*)d_in[2];
    const float* Wxf_w = (const float*)d_in[3];
    const float* Wxf_b = (const float*)d_in[4];
    const float* Whf_w = (const float*)d_in[5];
    const float* Wxb_w = (const float*)d_in[6];
    const float* Wxb_b = (const float*)d_in[7];
    const float* Whb_w = (const float*)d_in[8];

    float* y  = (float*)d_out;
    float* hT = y + (size_t)Bsz * Tt * 2 * Hh;

    const int RNN_SMEM = 2 * 64 * HPAD * 2 + 8 * 512 * 4;   // 149504 B
    cudaFuncSetAttribute(rnn_tc_kernel,
                         cudaFuncAttributeMaxDynamicSharedMemorySize,
                         RNN_SMEM);
    cudaFuncSetAttribute(xproj_tc_kernel,
                         cudaFuncAttributeMaxDynamicSharedMemorySize,
                         2 * ST_SIZE * 2);

    init_kernel<<<64, 512>>>(h0_f, h0_b);
    split_x_kernel<<<16384, 256>>>(x);
    split_w_kernel<<<512, 256>>>(Wxf_w, Wxb_w, Wxf_b, Wxb_b);

    dim3 grid(1024 / 128, 32768 / 128);
    xproj_tc_kernel<<<grid, 256, 2 * ST_SIZE * 2>>>(y);

    rnn_tc_kernel<<<128, 256, RNN_SMEM>>>(Whf_w, Whb_w, y, hT);
    (void)in_sizes; (void)n_in; (void)out_size;
}